// round 8
// baseline (speedup 1.0000x reference)
#include <cuda_runtime.h>
#include <math.h>

#define B_DIM 2048
#define T_DIM 256
#define IN_DIM 128
#define H_DIM 256
#define G3 768   // 3*H

typedef unsigned long long ull;

// Scratch. h buffers stored TRANSPOSED: [k=256][B=2048], so the recurrent
// GEMM's m-pairs are contiguous in gmem (coalesced float4 smem fill).
__device__ float g_gi[(size_t)B_DIM * T_DIM * G3];   // [B][T][768]
__device__ float g_h0[(size_t)H_DIM * B_DIM];        // hT double-buffer A
__device__ float g_h1[(size_t)H_DIM * B_DIM];        // hT double-buffer B

// ---------------------------------------------------------------------------
// Packed fp32x2 helpers (sm_100+). Each half is an independent IEEE fp32 FMA
// with single rounding -> bit-identical to scalar FFMA chains.
// ---------------------------------------------------------------------------
__device__ __forceinline__ void ffma2(ull &d, ull a, ull b) {
    asm("fma.rn.f32x2 %0, %1, %2, %0;" : "+l"(d) : "l"(a), "l"(b));
}
__device__ __forceinline__ void unpack2(ull v, float &x, float &y) {
    asm("mov.b64 {%0, %1}, %2;" : "=f"(x), "=f"(y) : "l"(v));
}

// ---------------------------------------------------------------------------
// XLA f32 tanh (Eigen rational poly, FMA-contracted) — bit-exact vs reference
// ---------------------------------------------------------------------------
__device__ __forceinline__ float tanh_xla(float x) {
    const float kClamp = 7.90531110763549805f;
    float xc = fminf(fmaxf(x, -kClamp), kClamp);

    const float a1  = 4.89352455891786e-03f;
    const float a3  = 6.37261928875436e-04f;
    const float a5  = 1.48572235717979e-05f;
    const float a7  = 5.12229709037114e-08f;
    const float a9  = -8.60467152213735e-11f;
    const float a11 = 2.00018790482477e-13f;
    const float a13 = -2.76076847742355e-16f;
    const float b0  = 4.89352518554385e-03f;
    const float b2  = 2.26843463243900e-03f;
    const float b4  = 1.18534705686654e-04f;
    const float b6  = 1.19825839466702e-06f;

    float x2 = __fmul_rn(xc, xc);

    float p = a13;
    p = fmaf(x2, p, a11);
    p = fmaf(x2, p, a9);
    p = fmaf(x2, p, a7);
    p = fmaf(x2, p, a5);
    p = fmaf(x2, p, a3);
    p = fmaf(x2, p, a1);
    float num = __fmul_rn(xc, p);

    float q = b6;
    q = fmaf(x2, q, b4);
    q = fmaf(x2, q, b2);
    q = fmaf(x2, q, b0);

    float ratio = __fdiv_rn(num, q);
    return (fabsf(x) < 0.0004f) ? x : ratio;
}

__device__ __forceinline__ float sigmoid_xla(float x) {
    float t = tanh_xla(__fmul_rn(0.5f, x));
    return fmaf(0.5f, t, 0.5f);
}

// ---------------------------------------------------------------------------
// gi GEMM (r6-proven, verbatim): C[M,768] = A[M,K] * W[768,K]^T, FFMA2 m-pairs
// ---------------------------------------------------------------------------
template<int K>
__global__ __launch_bounds__(128) void sgemm_nt2(
    const float* __restrict__ A, const float* __restrict__ W, float* __restrict__ C)
{
    __shared__ alignas(8) float As[16][66];
    __shared__ float Ws[16][66];

    const int tid = threadIdx.x;
    const int tn  = tid & 15;
    const int tm  = tid >> 4;
    const size_t m0 = (size_t)blockIdx.x * 64;
    const int    n0 = blockIdx.y * 64;

    const int lk = tid & 15;
    const int lm = tid >> 4;

    ull acc[4][4];
#pragma unroll
    for (int p = 0; p < 4; p++)
#pragma unroll
        for (int j = 0; j < 4; j++) acc[p][j] = 0ULL;

#pragma unroll 1
    for (int k0 = 0; k0 < K; k0 += 16) {
#pragma unroll
        for (int it = 0; it < 8; it++) {
            int m = lm + it * 8;
            As[lk][m] = A[(m0 + m) * K + (k0 + lk)];
            Ws[lk][m] = W[(size_t)(n0 + m) * K + (k0 + lk)];
        }
        __syncthreads();
#pragma unroll
        for (int kk = 0; kk < 16; kk++) {
            ull a[4];
#pragma unroll
            for (int p = 0; p < 4; p++)
                a[p] = *(const ull*)&As[kk][tm * 8 + 2 * p];
#pragma unroll
            for (int j = 0; j < 4; j++) {
                ull w2;
                asm("mov.b64 %0, {%1, %1};" : "=l"(w2) : "f"(Ws[kk][tn * 4 + j]));
#pragma unroll
                for (int p = 0; p < 4; p++)
                    ffma2(acc[p][j], a[p], w2);
            }
        }
        __syncthreads();
    }

#pragma unroll
    for (int p = 0; p < 4; p++) {
        size_t r0 = m0 + tm * 8 + 2 * p;
#pragma unroll
        for (int j = 0; j < 4; j++) {
            float lo, hi;
            unpack2(acc[p][j], lo, hi);
            C[r0 * G3 + (n0 + tn * 4 + j)]       = lo;
            C[(r0 + 1) * G3 + (n0 + tn * 4 + j)] = hi;
        }
    }
}

// ---------------------------------------------------------------------------
// Fused GRU step, full-K smem (single fill + single barrier per step).
// Block: 256 threads, tile [64 m x 16 hc x 3 gates], K=256 entirely in smem.
//   As2: [256][32] ull   (h pairs, pair-major == natural for transposed h)
//   Ws2: [48][257] ull   (pre-duplicated W, odd stride -> conflict-free reads)
// Thread tile: 2 m-pairs x 3 gates = 6 FFMA2 per kk, 5 LDS.64 per kk.
// ---------------------------------------------------------------------------
#define WS_STRIDE 257
#define SMEM_ULLS (8192 + 48 * WS_STRIDE)
#define SMEM_BYTES (SMEM_ULLS * 8)

__global__ __launch_bounds__(256) void gru_step(
    const float* __restrict__ gi_all,  // [B][T][768]
    const float* __restrict__ Whh,     // [768, 256]
    const float* __restrict__ b_ih, const float* __restrict__ b_hh,
    const float* __restrict__ hT_in,   // [256][B]
    float* __restrict__ hT_out,        // [256][B]
    int t, float* __restrict__ out, int is_last)
{
    extern __shared__ ull sm[];
    ull* As2 = sm;           // As2[kk*32 + mpair]
    ull* Ws2 = sm + 8192;    // Ws2[col*257 + kk]

    const int tid = threadIdx.x;
    const int tn  = tid & 15;          // hc within tile
    const int tm  = tid >> 4;          // 0..15
    const int m0  = blockIdx.x * 64;
    const int h0  = blockIdx.y * 16;
    const int hc  = h0 + tn;

    // ---- fill h tile: 4096 float4 copies, fully coalesced both sides ----
#pragma unroll
    for (int i = 0; i < 16; i++) {
        int e  = tid + i * 256;        // 0..4095
        int kk = e >> 4;
        int q  = e & 15;
        float4 v = *(const float4*)&hT_in[(size_t)kk * B_DIM + m0 + q * 4];
        ((float4*)&As2[kk * 32])[q] = v;
    }
    // ---- fill dup'd W tile: 3072 float4 loads, 4 dup float2 stores each ----
#pragma unroll
    for (int i = 0; i < 12; i++) {
        int e    = tid + i * 256;      // 0..3071
        int col  = e >> 6;             // 0..47
        int kq   = e & 63;             // k quad
        int gate = col >> 4;
        int hcc  = h0 + (col & 15);
        float4 v = *(const float4*)&Whh[((size_t)gate * H_DIM + hcc) * H_DIM + kq * 4];
        float2* dst = (float2*)&Ws2[col * WS_STRIDE + kq * 4];
        dst[0] = make_float2(v.x, v.x);
        dst[1] = make_float2(v.y, v.y);
        dst[2] = make_float2(v.z, v.z);
        dst[3] = make_float2(v.w, v.w);
    }

    // ---- prefetch gi for this thread's 4 outputs (hidden behind compute) ----
    float gir[4], giz[4], gin[4];
#pragma unroll
    for (int p = 0; p < 2; p++)
#pragma unroll
        for (int half = 0; half < 2; half++) {
            int m = m0 + (p * 16 + tm) * 2 + half;
            const float* g = gi_all + ((size_t)m * T_DIM + t) * G3;
            int ix = p * 2 + half;
            gir[ix] = g[hc];
            giz[ix] = g[hc + H_DIM];
            gin[ix] = g[hc + 2 * H_DIM];
        }

    __syncthreads();

    // ---- main loop: 256 kk, no barriers, 5 LDS.64 + 6 FFMA2 per kk ----
    ull acc[3][2];
#pragma unroll
    for (int g = 0; g < 3; g++) { acc[g][0] = 0ULL; acc[g][1] = 0ULL; }

    const ull* wr = &Ws2[(0 * 16 + tn) * WS_STRIDE];
    const ull* wz = &Ws2[(1 * 16 + tn) * WS_STRIDE];
    const ull* wn = &Ws2[(2 * 16 + tn) * WS_STRIDE];

#pragma unroll 16
    for (int kk = 0; kk < H_DIM; kk++) {
        ull a0 = As2[kk * 32 + tm];
        ull a1 = As2[kk * 32 + 16 + tm];
        ull w0 = wr[kk];
        ull w1 = wz[kk];
        ull w2 = wn[kk];
        ffma2(acc[0][0], a0, w0); ffma2(acc[0][1], a1, w0);
        ffma2(acc[1][0], a0, w1); ffma2(acc[1][1], a1, w1);
        ffma2(acc[2][0], a0, w2); ffma2(acc[2][1], a1, w2);
    }

    // ---- epilogue: exact XLA combine + sign ----
    const float b_ir = b_ih[hc], b_iz = b_ih[hc + H_DIM], b_in = b_ih[hc + 2 * H_DIM];
    const float b_hr = b_hh[hc], b_hz = b_hh[hc + H_DIM], b_hn = b_hh[hc + 2 * H_DIM];

#pragma unroll
    for (int p = 0; p < 2; p++) {
        float gr[2], gz[2], gn[2], hp[2];
        unpack2(acc[0][p], gr[0], gr[1]);
        unpack2(acc[1][p], gz[0], gz[1]);
        unpack2(acc[2][p], gn[0], gn[1]);
        // h_prev from the smem h tile (row k = hc holds h_in[m][hc])
        unpack2(As2[hc * 32 + p * 16 + tm], hp[0], hp[1]);
#pragma unroll
        for (int half = 0; half < 2; half++) {
            int m  = m0 + (p * 16 + tm) * 2 + half;
            int ix = p * 2 + half;

            float i_r = __fadd_rn(gir[ix], b_ir);
            float i_z = __fadd_rn(giz[ix], b_iz);
            float i_n = __fadd_rn(gin[ix], b_in);
            float h_r = __fadd_rn(gr[half], b_hr);
            float h_z = __fadd_rn(gz[half], b_hz);
            float h_n = __fadd_rn(gn[half], b_hn);

            float r = sigmoid_xla(__fadd_rn(i_r, h_r));
            float z = sigmoid_xla(__fadd_rn(i_z, h_z));
            float n = tanh_xla(fmaf(r, h_n, i_n));

            float one_minus_z = __fsub_rn(1.0f, z);
            float zh   = __fmul_rn(z, hp[half]);
            float hnew = fmaf(one_minus_z, n, zh);

            float s = (hnew > 0.0f) ? 1.0f : ((hnew < 0.0f) ? -1.0f : 0.0f);

            hT_out[(size_t)hc * B_DIM + m] = s;
            if (is_last) out[(size_t)m * H_DIM + hc] = s;
        }
    }
}

extern "C" void kernel_launch(void* const* d_in, const int* in_sizes, int n_in,
                              void* d_out, int out_size)
{
    const float* x   = (const float*)d_in[0];  // [2048, 256, 128]
    const float* Wih = (const float*)d_in[1];  // [768, 128]
    const float* Whh = (const float*)d_in[2];  // [768, 256]
    const float* bih = (const float*)d_in[3];  // [768]
    const float* bhh = (const float*)d_in[4];  // [768]
    float* out = (float*)d_out;                // [2048, 256]

    float *gi_p, *h0_p, *h1_p;
    cudaGetSymbolAddress((void**)&gi_p, g_gi);
    cudaGetSymbolAddress((void**)&h0_p, g_h0);
    cudaGetSymbolAddress((void**)&h1_p, g_h1);

    cudaFuncSetAttribute(gru_step, cudaFuncAttributeMaxDynamicSharedMemorySize,
                         SMEM_BYTES);

    cudaMemsetAsync(h0_p, 0, sizeof(float) * (size_t)H_DIM * B_DIM);

    // Phase 1: gi = X @ W_ih^T (M = B*T = 524288, K = 128).
    {
        dim3 grid((B_DIM * T_DIM) / 64, G3 / 64);
        sgemm_nt2<IN_DIM><<<grid, 128>>>(x, Wih, gi_p);
    }

    // Phase 2: fused sequential recurrence (double-buffered transposed h).
    {
        dim3 grid(B_DIM / 64, H_DIM / 16);
        float* ha = h0_p;
        float* hb = h1_p;
        for (int t = 0; t < T_DIM; t++) {
            gru_step<<<grid, 256, SMEM_BYTES>>>(gi_p, Whh, bih, bhh, ha, hb, t, out,
                                                (t == T_DIM - 1) ? 1 : 0);
            float* tmp = ha; ha = hb; hb = tmp;
        }
    }
}

// round 9
// speedup vs baseline: 1.4564x; 1.4564x over previous
#include <cuda_runtime.h>
#include <math.h>

#define B_DIM 2048
#define T_DIM 256
#define IN_DIM 128
#define H_DIM 256
#define G3 768   // 3*H

typedef unsigned long long ull;

// Scratch (static device arrays)
__device__ float g_gi[(size_t)B_DIM * T_DIM * G3];   // [B][T][768]
__device__ float g_WhhT[(size_t)H_DIM * G3];         // [256][768]  (k-major W)

// ---------------------------------------------------------------------------
// Packed fp32x2 helpers. Each half is an independent IEEE fp32 FMA with
// single rounding -> bit-identical to scalar FFMA chains.
// ---------------------------------------------------------------------------
__device__ __forceinline__ ull dup2(float x) {
    ull r; asm("mov.b64 %0, {%1, %1};" : "=l"(r) : "f"(x)); return r;
}
__device__ __forceinline__ void ffma2(ull &d, ull a, ull b) {
    asm("fma.rn.f32x2 %0, %1, %2, %0;" : "+l"(d) : "l"(a), "l"(b));
}
__device__ __forceinline__ void unpack2(ull v, float &x, float &y) {
    asm("mov.b64 {%0, %1}, %2;" : "=f"(x), "=f"(y) : "l"(v));
}

// ---------------------------------------------------------------------------
// XLA f32 tanh (Eigen rational poly, FMA-contracted) — bit-exact vs reference
// ---------------------------------------------------------------------------
__device__ __forceinline__ float tanh_xla(float x) {
    const float kClamp = 7.90531110763549805f;
    float xc = fminf(fmaxf(x, -kClamp), kClamp);

    const float a1  = 4.89352455891786e-03f;
    const float a3  = 6.37261928875436e-04f;
    const float a5  = 1.48572235717979e-05f;
    const float a7  = 5.12229709037114e-08f;
    const float a9  = -8.60467152213735e-11f;
    const float a11 = 2.00018790482477e-13f;
    const float a13 = -2.76076847742355e-16f;
    const float b0  = 4.89352518554385e-03f;
    const float b2  = 2.26843463243900e-03f;
    const float b4  = 1.18534705686654e-04f;
    const float b6  = 1.19825839466702e-06f;

    float x2 = __fmul_rn(xc, xc);

    float p = a13;
    p = fmaf(x2, p, a11);
    p = fmaf(x2, p, a9);
    p = fmaf(x2, p, a7);
    p = fmaf(x2, p, a5);
    p = fmaf(x2, p, a3);
    p = fmaf(x2, p, a1);
    float num = __fmul_rn(xc, p);

    float q = b6;
    q = fmaf(x2, q, b4);
    q = fmaf(x2, q, b2);
    q = fmaf(x2, q, b0);

    float ratio = __fdiv_rn(num, q);
    return (fabsf(x) < 0.0004f) ? x : ratio;
}

__device__ __forceinline__ float sigmoid_xla(float x) {
    float t = tanh_xla(__fmul_rn(0.5f, x));
    return fmaf(0.5f, t, 0.5f);
}

// ---------------------------------------------------------------------------
// One-off transpose: WhhT[k][n] = Whh[n][k]   (768x256 -> 256x768)
// ---------------------------------------------------------------------------
__global__ void transpose_whh(const float* __restrict__ Whh, float* __restrict__ WhhT)
{
    int idx = blockIdx.x * blockDim.x + threadIdx.x;   // 0..196607
    int k = idx / G3;
    int n = idx - k * G3;
    WhhT[idx] = Whh[(size_t)n * H_DIM + k];
}

// ---------------------------------------------------------------------------
// gi GEMM (r6-proven, verbatim): C[M,768] = A[M,K] * W[768,K]^T, FFMA2 m-pairs
// ---------------------------------------------------------------------------
template<int K>
__global__ __launch_bounds__(128) void sgemm_nt2(
    const float* __restrict__ A, const float* __restrict__ W, float* __restrict__ C)
{
    __shared__ alignas(8) float As[16][66];
    __shared__ float Ws[16][66];

    const int tid = threadIdx.x;
    const int tn  = tid & 15;
    const int tm  = tid >> 4;
    const size_t m0 = (size_t)blockIdx.x * 64;
    const int    n0 = blockIdx.y * 64;

    const int lk = tid & 15;
    const int lm = tid >> 4;

    ull acc[4][4];
#pragma unroll
    for (int p = 0; p < 4; p++)
#pragma unroll
        for (int j = 0; j < 4; j++) acc[p][j] = 0ULL;

#pragma unroll 1
    for (int k0 = 0; k0 < K; k0 += 16) {
#pragma unroll
        for (int it = 0; it < 8; it++) {
            int m = lm + it * 8;
            As[lk][m] = A[(m0 + m) * K + (k0 + lk)];
            Ws[lk][m] = W[(size_t)(n0 + m) * K + (k0 + lk)];
        }
        __syncthreads();
#pragma unroll
        for (int kk = 0; kk < 16; kk++) {
            ull a[4];
#pragma unroll
            for (int p = 0; p < 4; p++)
                a[p] = *(const ull*)&As[kk][tm * 8 + 2 * p];
#pragma unroll
            for (int j = 0; j < 4; j++) {
                ull w2 = dup2(Ws[kk][tn * 4 + j]);
#pragma unroll
                for (int p = 0; p < 4; p++)
                    ffma2(acc[p][j], a[p], w2);
            }
        }
        __syncthreads();
    }

#pragma unroll
    for (int p = 0; p < 4; p++) {
        size_t r0 = m0 + tm * 8 + 2 * p;
#pragma unroll
        for (int j = 0; j < 4; j++) {
            float lo, hi;
            unpack2(acc[p][j], lo, hi);
            C[r0 * G3 + (n0 + tn * 4 + j)]       = lo;
            C[(r0 + 1) * G3 + (n0 + tn * 4 + j)] = hi;
        }
    }
}

// ---------------------------------------------------------------------------
// Persistent GRU: each block owns 16 batch rows for ALL 256 timesteps.
// h lives block-locally (smem + regs); W streams from L2 directly to regs;
// gi is cp.async-prefetched per step. 128 blocks x 256 threads.
// Thread: mg = tid>>7 selects m-half (8 rows = 4 FFMA2 pairs),
//         tn = tid&127 selects hc pair {2tn, 2tn+1}; 3 gates per hc.
// ---------------------------------------------------------------------------
#define MB 16
#define HS_STRIDE 34                         // floats per h_sm k-row (8B-aligned, store conflicts 4-way)
#define SM_H_FLOATS (H_DIM * HS_STRIDE)      // 8704
#define SM_GI_FLOATS (MB * G3)               // 12288
#define SM_TOTAL_BYTES ((SM_H_FLOATS + SM_GI_FLOATS) * 4)   // 83968

__global__ __launch_bounds__(256, 1) void gru_persist(
    const float* __restrict__ gi_all,   // [B][T][768]
    const float* __restrict__ WhhT,     // [256][768]
    const float* __restrict__ b_ih, const float* __restrict__ b_hh,
    float* __restrict__ out)            // [B][256]
{
    extern __shared__ float sm[];
    float* h_sm  = sm;                  // [256][HS_STRIDE]
    float* gi_sm = sm + SM_H_FLOATS;    // [16][768]

    const int tid = threadIdx.x;
    const int tn  = tid & 127;
    const int mg  = tid >> 7;           // 0/1 -> m rows mg*8 .. mg*8+7
    const int hc0 = 2 * tn;
    const int m0  = blockIdx.x * MB;

    // zero h tile
    for (int i = tid; i < SM_H_FLOATS; i += 256) h_sm[i] = 0.0f;

    // biases for this thread's two hc columns
    float bir[2], biz[2], bin[2], bhr[2], bhz[2], bhn[2];
#pragma unroll
    for (int w = 0; w < 2; w++) {
        int hc = hc0 + w;
        bir[w] = b_ih[hc]; biz[w] = b_ih[hc + H_DIM]; bin[w] = b_ih[hc + 2 * H_DIM];
        bhr[w] = b_hh[hc]; bhz[w] = b_hh[hc + H_DIM]; bhn[w] = b_hh[hc + 2 * H_DIM];
    }

    // previous h for this thread's 16 outputs, kept in registers
    float hprev[2][8];
#pragma unroll
    for (int w = 0; w < 2; w++)
#pragma unroll
        for (int ml = 0; ml < 8; ml++) hprev[w][ml] = 0.0f;

    __syncthreads();

    for (int t = 0; t < T_DIM; t++) {
        // ---- prefetch this step's gi tile (16 x 768) via cp.async ----
#pragma unroll
        for (int i = 0; i < 12; i++) {
            int c  = tid + i * 256;          // 0..3071 (16B chunks)
            int mm = c / 192;
            int j  = c - mm * 192;
            const float* src = gi_all + ((size_t)(m0 + mm) * T_DIM + t) * G3 + j * 4;
            float* dst = gi_sm + mm * G3 + j * 4;
            unsigned daddr = (unsigned)__cvta_generic_to_shared(dst);
            asm volatile("cp.async.ca.shared.global [%0], [%1], 16;"
                         :: "r"(daddr), "l"(src) : "memory");
        }
        asm volatile("cp.async.commit_group;" ::: "memory");

        // ---- recurrent GEMM: 256 kk, h from smem (broadcast), W from L2 ----
        ull acc[3][2][4];   // [gate][hc-half][m-pair]
#pragma unroll
        for (int g = 0; g < 3; g++)
#pragma unroll
            for (int w = 0; w < 2; w++)
#pragma unroll
                for (int p = 0; p < 4; p++) acc[g][w][p] = 0ULL;

        const float* wbase = WhhT + hc0;
#pragma unroll 4
        for (int kk = 0; kk < H_DIM; kk++) {
            const float* wrow = wbase + (size_t)kk * G3;
            float2 wr = *(const float2*)(wrow);
            float2 wz = *(const float2*)(wrow + H_DIM);
            float2 wn = *(const float2*)(wrow + 2 * H_DIM);
            const float* ar = h_sm + kk * HS_STRIDE + mg * 8;
            ull a0 = *(const ull*)(ar);
            ull a1 = *(const ull*)(ar + 2);
            ull a2 = *(const ull*)(ar + 4);
            ull a3 = *(const ull*)(ar + 6);
            ull w;
            w = dup2(wr.x); ffma2(acc[0][0][0],a0,w); ffma2(acc[0][0][1],a1,w); ffma2(acc[0][0][2],a2,w); ffma2(acc[0][0][3],a3,w);
            w = dup2(wr.y); ffma2(acc[0][1][0],a0,w); ffma2(acc[0][1][1],a1,w); ffma2(acc[0][1][2],a2,w); ffma2(acc[0][1][3],a3,w);
            w = dup2(wz.x); ffma2(acc[1][0][0],a0,w); ffma2(acc[1][0][1],a1,w); ffma2(acc[1][0][2],a2,w); ffma2(acc[1][0][3],a3,w);
            w = dup2(wz.y); ffma2(acc[1][1][0],a0,w); ffma2(acc[1][1][1],a1,w); ffma2(acc[1][1][2],a2,w); ffma2(acc[1][1][3],a3,w);
            w = dup2(wn.x); ffma2(acc[2][0][0],a0,w); ffma2(acc[2][0][1],a1,w); ffma2(acc[2][0][2],a2,w); ffma2(acc[2][0][3],a3,w);
            w = dup2(wn.y); ffma2(acc[2][1][0],a0,w); ffma2(acc[2][1][1],a1,w); ffma2(acc[2][1][2],a2,w); ffma2(acc[2][1][3],a3,w);
        }

        asm volatile("cp.async.wait_group 0;" ::: "memory");
        __syncthreads();   // gi ready; all h_sm reads of this step complete

        // ---- epilogue: exact XLA combine + sign (bit-exact, unchanged) ----
        float snew[2][8];
#pragma unroll
        for (int hw = 0; hw < 2; hw++) {
            const int hc = hc0 + hw;
#pragma unroll
            for (int p = 0; p < 4; p++) {
                float gr2[2], gz2[2], gn2[2];
                unpack2(acc[0][hw][p], gr2[0], gr2[1]);
                unpack2(acc[1][hw][p], gz2[0], gz2[1]);
                unpack2(acc[2][hw][p], gn2[0], gn2[1]);
#pragma unroll
                for (int half = 0; half < 2; half++) {
                    int ml = 2 * p + half;               // 0..7
                    const float* gi = gi_sm + (mg * 8 + ml) * G3;

                    float i_r = __fadd_rn(gi[hc],             bir[hw]);
                    float i_z = __fadd_rn(gi[hc +     H_DIM], biz[hw]);
                    float i_n = __fadd_rn(gi[hc + 2 * H_DIM], bin[hw]);
                    float h_r = __fadd_rn(gr2[half], bhr[hw]);
                    float h_z = __fadd_rn(gz2[half], bhz[hw]);
                    float h_n = __fadd_rn(gn2[half], bhn[hw]);

                    float r = sigmoid_xla(__fadd_rn(i_r, h_r));
                    float z = sigmoid_xla(__fadd_rn(i_z, h_z));
                    float n = tanh_xla(fmaf(r, h_n, i_n));

                    float omz  = __fsub_rn(1.0f, z);
                    float zh   = __fmul_rn(z, hprev[hw][ml]);
                    float hnew = fmaf(omz, n, zh);

                    float s = (hnew > 0.0f) ? 1.0f : ((hnew < 0.0f) ? -1.0f : 0.0f);
                    snew[hw][ml]  = s;
                    hprev[hw][ml] = s;
                }
            }
        }

        // write new h into h_sm (k-row = hc, col = m). No race: epilogue reads
        // only gi_sm/regs, and the barrier above ended all gemm reads.
#pragma unroll
        for (int hw = 0; hw < 2; hw++) {
            const int hc = hc0 + hw;
#pragma unroll
            for (int ml = 0; ml < 8; ml++)
                h_sm[hc * HS_STRIDE + mg * 8 + ml] = snew[hw][ml];
        }

        if (t == T_DIM - 1) {
#pragma unroll
            for (int hw = 0; hw < 2; hw++)
#pragma unroll
                for (int ml = 0; ml < 8; ml++)
                    out[(size_t)(m0 + mg * 8 + ml) * H_DIM + hc0 + hw] = snew[hw][ml];
        }

        __syncthreads();   // new h visible before next step's gemm
    }
}

extern "C" void kernel_launch(void* const* d_in, const int* in_sizes, int n_in,
                              void* d_out, int out_size)
{
    const float* x   = (const float*)d_in[0];  // [2048, 256, 128]
    const float* Wih = (const float*)d_in[1];  // [768, 128]
    const float* Whh = (const float*)d_in[2];  // [768, 256]
    const float* bih = (const float*)d_in[3];  // [768]
    const float* bhh = (const float*)d_in[4];  // [768]
    float* out = (float*)d_out;                // [2048, 256]

    float *gi_p, *wt_p;
    cudaGetSymbolAddress((void**)&gi_p, g_gi);
    cudaGetSymbolAddress((void**)&wt_p, g_WhhT);

    cudaFuncSetAttribute(gru_persist, cudaFuncAttributeMaxDynamicSharedMemorySize,
                         SM_TOTAL_BYTES);

    // Prep: transpose Whh -> [k][768]
    transpose_whh<<<(H_DIM * G3) / 256, 256>>>(Whh, wt_p);

    // Phase 1: gi = X @ W_ih^T  (M = B*T = 524288, K = 128) -> [B][T][768]
    {
        dim3 grid((B_DIM * T_DIM) / 64, G3 / 64);
        sgemm_nt2<IN_DIM><<<grid, 128>>>(x, Wih, gi_p);
    }

    // Phase 2: persistent recurrence — one kernel for all 256 steps.
    gru_persist<<<B_DIM / MB, 256, SM_TOTAL_BYTES>>>(gi_p, wt_p, bih, bhh, out);
}